// round 3
// baseline (speedup 1.0000x reference)
#include <cuda_runtime.h>
#include <math.h>

#define DIM 512
#define MARGIN 1.0f
#define RULE_WEIGHT 0.5f

#define MAX_B   1024
#define MAX_NEG 8192

// Scratch (allocation-free rule: __device__ globals)
__device__ float g_dpos[MAX_B];
__device__ float g_rule[MAX_B];
__device__ float g_dneg[MAX_NEG];
__device__ unsigned int g_ticket = 0;   // reset by last block each call

__device__ __forceinline__ float warp_red(float v) {
#pragma unroll
    for (int o = 16; o; o >>= 1) v += __shfl_xor_sync(0xffffffffu, v, o);
    return v;
}

// TransH distance, he/te register-resident (warp-collective).
// d = || (he - te + re) - c*w ||,  c = (he.w - te.w)/(w.w)
__device__ __forceinline__ float dist_from_regs(
    const float4 he[4], const float4 te[4],
    const float* __restrict__ rel, const float* __restrict__ nv,
    int r, int lane)
{
    const float4* w4  = reinterpret_cast<const float4*>(nv  + (size_t)r * DIM);
    const float4* re4 = reinterpret_cast<const float4*>(rel + (size_t)r * DIM);
    float4 w[4], re[4];
    float ww = 0.f, hw = 0.f, tw = 0.f;
#pragma unroll
    for (int i = 0; i < 4; i++) {
        w[i]  = w4[lane + 32 * i];
        re[i] = re4[lane + 32 * i];
        ww += w[i].x * w[i].x + w[i].y * w[i].y + w[i].z * w[i].z + w[i].w * w[i].w;
        hw += he[i].x * w[i].x + he[i].y * w[i].y + he[i].z * w[i].z + he[i].w * w[i].w;
        tw += te[i].x * w[i].x + te[i].y * w[i].y + te[i].z * w[i].z + te[i].w * w[i].w;
    }
    ww = warp_red(ww);
    hw = warp_red(hw);
    tw = warp_red(tw);
    float c = (hw - tw) / ww;
    float ss = 0.f;
#pragma unroll
    for (int i = 0; i < 4; i++) {
        float dx = he[i].x - te[i].x + re[i].x - c * w[i].x;
        float dy = he[i].y - te[i].y + re[i].y - c * w[i].y;
        float dz = he[i].z - te[i].z + re[i].z - c * w[i].z;
        float dw = he[i].w - te[i].w + re[i].w - c * w[i].w;
        ss += dx * dx + dy * dy + dz * dz + dw * dw;
    }
    ss = warp_red(ss);
    return sqrtf(ss);
}

// Flat warp-per-task (R1 structure) + last-block reduction fused in.
__global__ void __launch_bounds__(256)
fused_all(const int* __restrict__ pos, const int* __restrict__ neg,
          const int* __restrict__ rr1, const int* __restrict__ rr2,
          const float* __restrict__ rconf,
          const float* __restrict__ ent, const float* __restrict__ rel,
          const float* __restrict__ nv,
          float* __restrict__ out,
          int B, int NEG, int NR)
{
    int gw   = (blockIdx.x * blockDim.x + threadIdx.x) >> 5;
    int lane = threadIdx.x & 31;
    int tid  = threadIdx.x;

    // ---- Phase 1: independent warp-per-distance (no intra-block coupling) ----
    if (gw < B + NEG) {
        int h, r, t;
        bool is_pos = (gw < B);
        if (is_pos) {
            h = pos[3 * gw]; r = pos[3 * gw + 1]; t = pos[3 * gw + 2];
        } else {
            int k = gw - B;
            h = neg[3 * k]; r = neg[3 * k + 1]; t = neg[3 * k + 2];
        }

        const float4* he4 = reinterpret_cast<const float4*>(ent + (size_t)h * DIM);
        const float4* te4 = reinterpret_cast<const float4*>(ent + (size_t)t * DIM);
        float4 he[4], te[4];
#pragma unroll
        for (int i = 0; i < 4; i++) {
            he[i] = he4[lane + 32 * i];
            te[i] = te4[lane + 32 * i];
        }

        float d = dist_from_regs(he, te, rel, nv, r, lane);

        if (is_pos) {
            // Only rules with rule_r1[j] == r contribute; others are exact zeros.
            float racc = 0.f;
            for (int j = 0; j < NR; j++) {
                if (rr1[j] == r)
                    racc += rconf[j] * dist_from_regs(he, te, rel, nv, rr2[j], lane);
            }
            if (lane == 0) { g_dpos[gw] = d; g_rule[gw] = racc; }
        } else {
            if (lane == 0) g_dneg[gw - B] = d;
        }
    }

    // ---- Phase 2: last block reduces (data is freshly written -> L2 hot) ----
    __syncthreads();           // block's writes issued
    __threadfence();           // publish to L2/global

    __shared__ bool s_last;
    if (tid == 0) {
        unsigned int ticket = atomicAdd(&g_ticket, 1u);
        s_last = (ticket == gridDim.x - 1);
    }
    __syncthreads();
    if (!s_last) return;

    __threadfence();           // acquire all blocks' writes

    int ratio = NEG / B;
    float acc = 0.f;
    for (int k = tid; k < NEG; k += blockDim.x) {
        float v = MARGIN + g_dpos[k / ratio] - g_dneg[k];
        acc += (v > 0.f) ? v : 0.f;
    }
    float racc = 0.f;
    for (int i = tid; i < B; i += blockDim.x) racc += g_rule[i];

    __shared__ float sb[256];
    __shared__ float sr[256];
    sb[tid] = acc; sr[tid] = racc;
    __syncthreads();
    for (int s = 128; s; s >>= 1) {
        if (tid < s) { sb[tid] += sb[tid + s]; sr[tid] += sr[tid + s]; }
        __syncthreads();
    }
    if (tid == 0) {
        out[0] = sb[0] / (float)NEG + RULE_WEIGHT * sr[0];
        g_ticket = 0;          // reset for next graph replay (deterministic)
    }
}

extern "C" void kernel_launch(void* const* d_in, const int* in_sizes, int n_in,
                              void* d_out, int out_size)
{
    const int*   pos   = (const int*)d_in[0];
    const int*   neg   = (const int*)d_in[1];
    const int*   rr1   = (const int*)d_in[2];
    const int*   rr2   = (const int*)d_in[3];
    const float* rconf = (const float*)d_in[4];
    const float* ent   = (const float*)d_in[5];
    const float* rel   = (const float*)d_in[6];
    const float* nv    = (const float*)d_in[7];

    int B   = in_sizes[0] / 3;
    int NEG = in_sizes[1] / 3;
    int NR  = in_sizes[2];

    int totalWarps = B + NEG;
    int blocks = (totalWarps * 32 + 255) / 256;

    fused_all<<<blocks, 256>>>(pos, neg, rr1, rr2, rconf, ent, rel, nv,
                               (float*)d_out, B, NEG, NR);
}

// round 4
// speedup vs baseline: 2.0172x; 2.0172x over previous
#include <cuda_runtime.h>
#include <math.h>

#define DIM 512
#define MARGIN 1.0f
#define RULE_WEIGHT 0.5f

#define MAX_B   1024
#define MAX_NEG 8192

// Scratch (allocation-free rule: __device__ globals)
__device__ float g_dpos[MAX_B];
__device__ float g_rule[MAX_B];
__device__ float g_dneg[MAX_NEG];

__device__ __forceinline__ float warp_red(float v) {
#pragma unroll
    for (int o = 16; o; o >>= 1) v += __shfl_xor_sync(0xffffffffu, v, o);
    return v;
}

// TransH distance from the register-resident difference hd = he - te.
// c = hd.w / w.w ;  d = || hd + re - c*w ||
__device__ __forceinline__ float dist_from_hd(
    const float4 hd[4],
    const float* __restrict__ rel, const float* __restrict__ nv,
    int r, int lane)
{
    const float4* w4  = reinterpret_cast<const float4*>(nv  + (size_t)r * DIM);
    const float4* re4 = reinterpret_cast<const float4*>(rel + (size_t)r * DIM);
    float4 w[4], re[4];
    float ww = 0.f, dw = 0.f;
#pragma unroll
    for (int i = 0; i < 4; i++) {
        w[i]  = w4[lane + 32 * i];
        re[i] = re4[lane + 32 * i];
        ww += w[i].x * w[i].x + w[i].y * w[i].y + w[i].z * w[i].z + w[i].w * w[i].w;
        dw += hd[i].x * w[i].x + hd[i].y * w[i].y + hd[i].z * w[i].z + hd[i].w * w[i].w;
    }
    ww = warp_red(ww);
    dw = warp_red(dw);
    float c = dw / ww;
    float ss = 0.f;
#pragma unroll
    for (int i = 0; i < 4; i++) {
        float dx = hd[i].x + re[i].x - c * w[i].x;
        float dy = hd[i].y + re[i].y - c * w[i].y;
        float dz = hd[i].z + re[i].z - c * w[i].z;
        float dw2 = hd[i].w + re[i].w - c * w[i].w;
        ss += dx * dx + dy * dy + dz * dz + dw2 * dw2;
    }
    ss = warp_red(ss);
    return sqrtf(ss);
}

// Flat warp-per-task: [0,B) = pos triples (+rule terms), [B,B+NEG) = negs.
// No intra-block coupling, no fences.
__global__ void __launch_bounds__(256)
dist_kernel(const int* __restrict__ pos, const int* __restrict__ neg,
            const int* __restrict__ rr1, const int* __restrict__ rr2,
            const float* __restrict__ rconf,
            const float* __restrict__ ent, const float* __restrict__ rel,
            const float* __restrict__ nv,
            int B, int NEG, int NR)
{
    int gw   = (blockIdx.x * blockDim.x + threadIdx.x) >> 5;
    int lane = threadIdx.x & 31;
    if (gw >= B + NEG) return;

    int h, r, t;
    bool is_pos = (gw < B);
    if (is_pos) {
        h = pos[3 * gw]; r = pos[3 * gw + 1]; t = pos[3 * gw + 2];
    } else {
        int k = gw - B;
        h = neg[3 * k]; r = neg[3 * k + 1]; t = neg[3 * k + 2];
    }

    const float4* he4 = reinterpret_cast<const float4*>(ent + (size_t)h * DIM);
    const float4* te4 = reinterpret_cast<const float4*>(ent + (size_t)t * DIM);
    float4 hd[4];
#pragma unroll
    for (int i = 0; i < 4; i++) {
        float4 a = he4[lane + 32 * i];
        float4 b = te4[lane + 32 * i];
        hd[i].x = a.x - b.x; hd[i].y = a.y - b.y;
        hd[i].z = a.z - b.z; hd[i].w = a.w - b.w;
    }

    float d = dist_from_hd(hd, rel, nv, r, lane);

    if (is_pos) {
        // Only rules with rule_r1[j] == r contribute (mask exact-zeros the rest).
        float racc = 0.f;
        for (int j = 0; j < NR; j++) {
            if (rr1[j] == r)
                racc += rconf[j] * dist_from_hd(hd, rel, nv, rr2[j], lane);
        }
        if (lane == 0) { g_dpos[gw] = d; g_rule[gw] = racc; }
    } else {
        if (lane == 0) g_dneg[gw - B] = d;
    }
}

// Single block, 1024 threads. d_pos staged in smem; d_neg read as float4 for
// full MLP in one latency round. Everything is L2-hot (just written).
__global__ void __launch_bounds__(1024)
final_reduce(float* __restrict__ out, int B, int NEG)
{
    __shared__ float s_dpos[MAX_B];
    __shared__ float s_part[32];
    __shared__ float s_partr[32];
    int tid = threadIdx.x;
    int ratio = NEG / B;

    float racc = 0.f;
    for (int i = tid; i < B; i += 1024) {
        s_dpos[i] = g_dpos[i];
        racc += g_rule[i];
    }
    __syncthreads();

    float acc = 0.f;
    const float4* n4 = reinterpret_cast<const float4*>(g_dneg);
    int nv4 = NEG >> 2;
    for (int q = tid; q < nv4; q += 1024) {
        float4 v = n4[q];
        int kb = 4 * q;
        float d0 = s_dpos[kb / ratio];
        float d1 = s_dpos[(kb + 1) / ratio];
        float d2 = s_dpos[(kb + 2) / ratio];
        float d3 = s_dpos[(kb + 3) / ratio];
        float v0 = MARGIN + d0 - v.x; acc += (v0 > 0.f) ? v0 : 0.f;
        float v1 = MARGIN + d1 - v.y; acc += (v1 > 0.f) ? v1 : 0.f;
        float v2 = MARGIN + d2 - v.z; acc += (v2 > 0.f) ? v2 : 0.f;
        float v3 = MARGIN + d3 - v.w; acc += (v3 > 0.f) ? v3 : 0.f;
    }
    for (int k = (nv4 << 2) + tid; k < NEG; k += 1024) {
        float v = MARGIN + s_dpos[k / ratio] - g_dneg[k];
        acc += (v > 0.f) ? v : 0.f;
    }

    acc  = warp_red(acc);
    racc = warp_red(racc);
    int wid = tid >> 5, lane = tid & 31;
    if (lane == 0) { s_part[wid] = acc; s_partr[wid] = racc; }
    __syncthreads();
    if (wid == 0) {
        float a = (lane < 32) ? s_part[lane]  : 0.f;
        float rr = (lane < 32) ? s_partr[lane] : 0.f;
        a  = warp_red(a);
        rr = warp_red(rr);
        if (lane == 0)
            out[0] = a / (float)NEG + RULE_WEIGHT * rr;
    }
}

extern "C" void kernel_launch(void* const* d_in, const int* in_sizes, int n_in,
                              void* d_out, int out_size)
{
    const int*   pos   = (const int*)d_in[0];
    const int*   neg   = (const int*)d_in[1];
    const int*   rr1   = (const int*)d_in[2];
    const int*   rr2   = (const int*)d_in[3];
    const float* rconf = (const float*)d_in[4];
    const float* ent   = (const float*)d_in[5];
    const float* rel   = (const float*)d_in[6];
    const float* nv    = (const float*)d_in[7];

    int B   = in_sizes[0] / 3;
    int NEG = in_sizes[1] / 3;
    int NR  = in_sizes[2];

    int totalWarps = B + NEG;
    int blocks = (totalWarps * 32 + 255) / 256;

    dist_kernel<<<blocks, 256>>>(pos, neg, rr1, rr2, rconf, ent, rel, nv, B, NEG, NR);
    final_reduce<<<1, 1024>>>((float*)d_out, B, NEG);
}